// round 10
// baseline (speedup 1.0000x reference)
#include <cuda_runtime.h>
#include <cuda_bf16.h>
#include <stdint.h>
#include <math.h>

#define VOCAB 32000
#define HID   512
#define EMB   256
#define NB    256
#define LEN   512

#define CL    8            // cluster size = h-tile CTAs per n-tile
#define NTILE 16           // n rows per block
#define HTILE 64           // h cols per block
#define GRID  128
#define NTHR  512
#define NSETS 4            // mbarrier round-robin sets (ABA safety)

typedef unsigned long long u64;

// Scratch (static device allocations are allowed; runtime allocs are not).
__device__ float g_P[VOCAB * HID];            // P = emb @ Wxh^T + b  (65.5 MB)
__device__ float g_h[2][NB * HID];            // ping-pong hidden state

// Packed fp32x2 ops (B300 packed pipe; ptxas never emits these from C++).
__device__ __forceinline__ u64 ffma2(u64 a, u64 b, u64 c) {
    u64 d;
    asm("fma.rn.f32x2 %0, %1, %2, %3;" : "=l"(d) : "l"(a), "l"(b), "l"(c));
    return d;
}
__device__ __forceinline__ u64 fadd2(u64 a, u64 b) {
    u64 d;
    asm("add.rn.f32x2 %0, %1, %2;" : "=l"(d) : "l"(a), "l"(b));
    return d;
}

// Local mbarrier wait, cluster-scope acquire (orders peer GMEM stores
// published by a cluster-scope release-arrive before our cp.async reads).
__device__ __forceinline__ void mbar_wait_cluster(unsigned addr, unsigned parity) {
    asm volatile(
        "{\n\t"
        ".reg .pred P;\n\t"
        "LW_%=:\n\t"
        "mbarrier.try_wait.parity.acquire.cluster.shared::cta.b64 P, [%0], %1;\n\t"
        "@!P bra LW_%=;\n\t"
        "}"
        :: "r"(addr), "r"(parity) : "memory");
}

// ---------------------------------------------------------------------------
// proj_kernel: g_P[v,h] = sum_e emb[v,e] * Wxh_w[h,e] + Wxh_b[h]   (FFMA2)
// ---------------------------------------------------------------------------
__global__ void proj_kernel(const float* __restrict__ emb,
                            const float* __restrict__ Wxh_w,
                            const float* __restrict__ Wxh_b) {
    const int K   = EMB;
    const int STR = EMB + 4;
    extern __shared__ float sm[];
    float* As  = sm;
    float* Ws  = sm + 32 * STR;
    float* red = sm + 64 * STR;

    const int tid = threadIdx.x;
    const int v0  = blockIdx.x * 32;
    const int h0  = blockIdx.y * 32;

    const int NV4 = 32 * (K / 4);
    for (int idx = tid; idx < NV4; idx += 256) {
        int r  = idx / (K / 4);
        int c4 = (idx % (K / 4)) * 4;
        *(float4*)&As[r * STR + c4] = *(const float4*)&emb[(size_t)(v0 + r) * K + c4];
        *(float4*)&Ws[r * STR + c4] = *(const float4*)&Wxh_w[(size_t)(h0 + r) * K + c4];
    }
    __syncthreads();

    const int lane = tid & 31, kg = tid >> 5;
    const int ln = lane & 7, lh = lane >> 3;
    const int kb = kg * (K / 8);

    u64 acc[4][8];
#pragma unroll
    for (int i = 0; i < 4; i++)
#pragma unroll
        for (int j = 0; j < 8; j++) acc[i][j] = 0ULL;

#pragma unroll 4
    for (int kk = 0; kk < K / 8; kk += 4) {
        float4 av[4], wv[8];
#pragma unroll
        for (int i = 0; i < 4; i++)
            av[i] = *(const float4*)&As[(ln + 8 * i) * STR + kb + kk];
#pragma unroll
        for (int j = 0; j < 8; j++)
            wv[j] = *(const float4*)&Ws[(lh + 4 * j) * STR + kb + kk];
#pragma unroll
        for (int i = 0; i < 4; i++) {
            u64 alo = ((const u64*)&av[i])[0], ahi = ((const u64*)&av[i])[1];
#pragma unroll
            for (int j = 0; j < 8; j++) {
                u64 wlo = ((const u64*)&wv[j])[0], whi = ((const u64*)&wv[j])[1];
                acc[i][j] = ffma2(alo, wlo, acc[i][j]);
                acc[i][j] = ffma2(ahi, whi, acc[i][j]);
            }
        }
    }

#pragma unroll
    for (int i = 0; i < 4; i++)
#pragma unroll
        for (int j = 0; j < 8; j++) {
            float2 f = *(float2*)&acc[i][j];
            red[kg * 1152 + (ln + 8 * i) * 36 + (lh + 4 * j)] = f.x + f.y;
        }
    __syncthreads();

    const int o_n = tid >> 3, o_h = (tid & 7) * 4;
    float4 s = make_float4(0.f, 0.f, 0.f, 0.f);
#pragma unroll
    for (int g = 0; g < 8; g++) {
        float4 p = *(const float4*)&red[g * 1152 + o_n * 36 + o_h];
        s.x += p.x; s.y += p.y; s.z += p.z; s.w += p.w;
    }
    float4 b4 = *(const float4*)&Wxh_b[h0 + o_h];
    s.x += b4.x; s.y += b4.y; s.z += b4.z; s.w += b4.w;
    *(float4*)&g_P[(size_t)(v0 + o_n) * HID + h0 + o_h] = s;
}

// ---------------------------------------------------------------------------
// rnn_kernel: ONE persistent clustered launch, all 512 timesteps.
//   128 CTAs = 16 clusters of 8; cluster = the 8 h-tile CTAs of one n-tile.
//   Sync = per-producer SMEM mbarriers (8 slots x NSETS sets per CTA).
//   Producer j, after step-t epilogue: mapa+arrive(release.cluster) on slot
//   [t&3][j] of all 8 cluster CTAs (one-way DSMEM, no L2 round trip).
//   Consumer warp w waits locally (try_wait acquire.cluster) on slot
//   [(t-1)&3][w>>1], then cp.async.cg's its slice from L2 (L1-bypassed,
//   so no stale-L1 hazard; cluster.sync only once at init).
//   Own-CTA warps get their slice through SMEM from the epilogue (no wait).
// ---------------------------------------------------------------------------
__global__ void __launch_bounds__(NTHR, 1) __cluster_dims__(CL, 1, 1)
rnn_kernel(const int*   __restrict__ X,
           const float* __restrict__ Whh_w,
           const float* __restrict__ Whh_b,
           float*       __restrict__ out)
{
    extern __shared__ float sm[];
    float*  sm_h   = sm;                       // [16 w][16 n][32 k]   32 KB
    float2* sm_red = (float2*)(sm + 16 * 512); // [16 kg][16 n][32 l]  64 KB
    // mbarriers: NSETS x CL u64 words after the 96 KB of data
    float*  sm_bar = sm + 16 * 512 + 16 * 512 * 2;

    const int tid   = threadIdx.x;
    const int w     = tid >> 5;
    const int lane  = tid & 31;
    const int tile  = blockIdx.x >> 3;         // n-tile id (cluster id)
    const int j_own = blockIdx.x & 7;          // own h-block id = cluster rank
    const int n0    = tile * NTILE;
    const int h0    = j_own * HTILE;
    const int hA    = h0 + 2 * lane;           // contiguous h pair
    const int hB    = hA + 1;

    const int  j_src   = w >> 1;               // producer this warp consumes
    const bool is_self = (j_src == j_own);

    // --- mbarrier init (count=1: exactly one arrive per slot per use) ------
    unsigned bar_u32;
    {
        unsigned a;
        asm("{ .reg .u64 t; cvta.to.shared.u64 t, %1; cvt.u32.u64 %0, t; }"
            : "=r"(a) : "l"(sm_bar));
        bar_u32 = a;
    }
    if (tid == 0) {
#pragma unroll
        for (int i = 0; i < NSETS * CL; i++)
            asm volatile("mbarrier.init.shared.b64 [%0], %1;"
                         :: "r"(bar_u32 + i * 8), "r"(1u) : "memory");
    }
    __syncthreads();
    // all cluster CTAs' barriers must be live before any remote arrive
    asm volatile("barrier.cluster.arrive.aligned;" ::: "memory");
    asm volatile("barrier.cluster.wait.aligned;" ::: "memory");

    // --- persistent weight registers: rows hA,hB, k in [32w, 32w+32) -------
    u64 wA[16], wB[16];
    {
        const u64* pa = (const u64*)&Whh_w[(size_t)hA * HID + w * 32];
        const u64* pb = (const u64*)&Whh_w[(size_t)hB * HID + w * 32];
#pragma unroll
        for (int i = 0; i < 16; i++) { wA[i] = pa[i]; wB[i] = pb[i]; }
    }

    unsigned int smem_w_base;
    {
        unsigned int a;
        asm("{ .reg .u64 t; cvta.to.shared.u64 t, %1; cvt.u32.u64 %0, t; }"
            : "=r"(a) : "l"(sm_h + w * 512));
        smem_w_base = a;
    }

    // epilogue ownership: thread (en, el) -> row n0+en, h-pair h0+2*el
    const int    en    = tid >> 5;
    const int    el    = tid & 31;
    const int    enab  = n0 + en;
    const float2 ebv   = *(const float2*)&Whh_b[h0 + 2 * el];
    // SMEM destination for own slice: warp 2*j_own + (el>=16), [n=en][kk=2el&31]
    float* sm_self = &sm_h[(2 * j_own + (el >> 4)) * 512 + en * 32 + ((2 * el) & 31)];

    // preload step-0 gather
    float2 pv;
    {
        int xid = __ldg(&X[enab * LEN]);
        pv = __ldg((const float2*)&g_P[(size_t)xid * HID + h0 + 2 * el]);
    }

    for (int t = 0; t < LEN; t++) {
        float* dst = (t == LEN - 1) ? out : ((t & 1) ? g_h[1] : g_h[0]);
        const float* hin = (t & 1) ? g_h[0] : g_h[1];

        float sA = 0.f, sB = 0.f;

        if (t > 0) {
            if (!is_self) {
                // --- wait locally for our single producer (acquire.cluster) -
                const int      s   = (t - 1) & 3;
                const unsigned par = (unsigned)(((t - 1) >> 2) & 1);
                mbar_wait_cluster(bar_u32 + (s * CL + j_src) * 8, par);

                // --- pull its 16n x 32k slice from L2 ------------------------
#pragma unroll
                for (int i = 0; i < 4; i++) {
                    int c  = i * 32 + lane;          // 16B chunk id (0..127)
                    int n  = c >> 3;
                    int kq = c & 7;
                    const float* src =
                        &hin[(size_t)(n0 + n) * HID + w * 32 + kq * 4];
                    asm volatile("cp.async.cg.shared.global [%0], [%1], 16;"
                                 :: "r"(smem_w_base + c * 16), "l"(src) : "memory");
                }
                asm volatile("cp.async.commit_group;" ::: "memory");
                asm volatile("cp.async.wait_group 0;" ::: "memory");
            }
            // (self warps: slice already in SMEM from last step's epilogue)

            // --- compute in two n-halves of 8 (register pressure) -----------
#pragma unroll
            for (int half = 0; half < 2; half++) {
                u64 aA[8], aB[8];
#pragma unroll
                for (int n = 0; n < 8; n++) { aA[n] = 0ULL; aB[n] = 0ULL; }
                const float* hp = sm_h + w * 512 + half * 8 * 32;
#pragma unroll
                for (int n = 0; n < 8; n++) {
                    const float4* row = (const float4*)(hp + n * 32);
                    u64 a0 = aA[n], a1 = aB[n];
#pragma unroll
                    for (int j = 0; j < 8; j++) {
                        float4 hv = row[j];
                        u64 lo = ((const u64*)&hv)[0];
                        u64 hi = ((const u64*)&hv)[1];
                        a0 = ffma2(lo, wA[2 * j],     a0);
                        a0 = ffma2(hi, wA[2 * j + 1], a0);
                        a1 = ffma2(lo, wB[2 * j],     a1);
                        a1 = ffma2(hi, wB[2 * j + 1], a1);
                    }
                    aA[n] = a0; aB[n] = a1;
                }
#pragma unroll
                for (int n = 0; n < 8; n++) {
                    float2 fa = *(float2*)&aA[n];
                    float2 fb = *(float2*)&aB[n];
                    sm_red[w * 512 + (half * 8 + n) * 32 + lane] =
                        make_float2(fa.x + fa.y, fb.x + fb.y);
                }
            }
            __syncthreads();

            // --- k-group reduction, packed f32x2 adds ------------------------
            u64 r1 = 0ULL, r2 = 0ULL;
#pragma unroll
            for (int g = 0; g < 16; g += 2) {
                u64 v0 = *(const u64*)&sm_red[g * 512 + tid];
                u64 v1 = *(const u64*)&sm_red[(g + 1) * 512 + tid];
                r1 = fadd2(r1, v0);
                r2 = fadd2(r2, v1);
            }
            u64 rt = fadd2(r1, r2);
            float2 rr = *(float2*)&rt;
            sA = rr.x; sB = rr.y;
        }

        // --- fused epilogue: bias + P + tanh; publish to GMEM + own SMEM -----
        float2 o;
        o.x = tanhf(sA + ebv.x + pv.x);
        o.y = tanhf(sB + ebv.y + pv.y);
        *(float2*)&dst[(size_t)enab * HID + h0 + 2 * el] = o;
        *(float2*)sm_self = o;                 // self-warps read this next step

        if (t < LEN - 1) {
            // prefetch next step's gather (g_P immutable; hides under publish)
            int xid2 = __ldg(&X[enab * LEN + t + 1]);
            pv = __ldg((const float2*)&g_P[(size_t)xid2 * HID + h0 + 2 * el]);

            __syncthreads();                   // all epilogue STG/STS issued
            if (tid == 0) {
                const int s = t & 3;
                unsigned mybar = bar_u32 + (s * CL + j_own) * 8;
#pragma unroll
                for (int r = 0; r < CL; r++) {
                    // release.cluster: makes this CTA's h stores (ordered by
                    // the syncthreads above) visible to rank r's acquire wait
                    asm volatile(
                        "{\n\t"
                        ".reg .b32 ra;\n\t"
                        "mapa.shared::cluster.u32 ra, %0, %1;\n\t"
                        "mbarrier.arrive.release.cluster.shared::cluster.b64 _, [ra];\n\t"
                        "}"
                        :: "r"(mybar), "r"(r) : "memory");
                }
            }
        }
    }

    // drain: no CTA may exit while peers could still target its SMEM barriers
    asm volatile("barrier.cluster.arrive.aligned;" ::: "memory");
    asm volatile("barrier.cluster.wait.aligned;" ::: "memory");
}

// ---------------------------------------------------------------------------
extern "C" void kernel_launch(void* const* d_in, const int* in_sizes, int n_in,
                              void* d_out, int out_size) {
    const int*   X     = (const int*)d_in[0];
    const float* emb   = (const float*)d_in[1];
    const float* Whh_w = (const float*)d_in[2];
    const float* Whh_b = (const float*)d_in[3];
    const float* Wxh_w = (const float*)d_in[4];
    const float* Wxh_b = (const float*)d_in[5];
    float* out = (float*)d_out;

    const size_t sm_proj = (size_t)(64 * (EMB + 4) + 8 * 32 * 36) * sizeof(float); // ~101 KB
    const size_t sm_rnn  = (size_t)(16 * 512) * sizeof(float)                      // 32 KB h
                         + (size_t)(16 * 512) * sizeof(float2)                     // 64 KB red
                         + (size_t)(NSETS * CL) * sizeof(u64);                     // 256 B bars
    cudaFuncSetAttribute(proj_kernel, cudaFuncAttributeMaxDynamicSharedMemorySize, (int)sm_proj);
    cudaFuncSetAttribute(rnn_kernel,  cudaFuncAttributeMaxDynamicSharedMemorySize, (int)sm_rnn);

    // 1) P = emb @ Wxh^T + Wxh_b
    proj_kernel<<<dim3(VOCAB / 32, HID / 32), 256, sm_proj>>>(emb, Wxh_w, Wxh_b);

    // 2) all 512 timesteps in one persistent clustered launch
    rnn_kernel<<<GRID, NTHR, sm_rnn>>>(X, Whh_w, Whh_b, out);
}

// round 11
// speedup vs baseline: 2.1539x; 2.1539x over previous
#include <cuda_runtime.h>
#include <cuda_bf16.h>
#include <stdint.h>
#include <math.h>

#define VOCAB 32000
#define HID   512
#define EMB   256
#define NB    256
#define LEN   512

#define CL    8            // h-tile CTAs per n-tile (flag group size)
#define NTILE 16           // n rows per block
#define HTILE 64           // h cols per block
#define NT    16           // number of n-tiles
#define GRID  128
#define NTHR  512

typedef unsigned long long u64;

// Scratch (static device allocations are allowed; runtime allocs are not).
__device__ float g_P[VOCAB * HID];            // P = emb @ Wxh^T + b  (65.5 MB)
__device__ float g_h[2][NB * HID];            // ping-pong hidden state
__device__ unsigned g_flag[NT * CL * 64];     // per-producer flags, 256B apart
__device__ unsigned g_cnt[NT * 64];           // end-of-kernel cleanup counters

// Packed fp32x2 ops (B300 packed pipe; ptxas never emits these from C++).
__device__ __forceinline__ u64 ffma2(u64 a, u64 b, u64 c) {
    u64 d;
    asm("fma.rn.f32x2 %0, %1, %2, %3;" : "=l"(d) : "l"(a), "l"(b), "l"(c));
    return d;
}
__device__ __forceinline__ u64 fadd2(u64 a, u64 b) {
    u64 d;
    asm("add.rn.f32x2 %0, %1, %2;" : "=l"(d) : "l"(a), "l"(b));
    return d;
}

// ---------------------------------------------------------------------------
// proj_kernel: g_P[v,h] = sum_e emb[v,e] * Wxh_w[h,e] + Wxh_b[h]   (FFMA2)
// ---------------------------------------------------------------------------
__global__ void proj_kernel(const float* __restrict__ emb,
                            const float* __restrict__ Wxh_w,
                            const float* __restrict__ Wxh_b) {
    const int K   = EMB;
    const int STR = EMB + 4;
    extern __shared__ float sm[];
    float* As  = sm;
    float* Ws  = sm + 32 * STR;
    float* red = sm + 64 * STR;

    const int tid = threadIdx.x;
    const int v0  = blockIdx.x * 32;
    const int h0  = blockIdx.y * 32;

    const int NV4 = 32 * (K / 4);
    for (int idx = tid; idx < NV4; idx += 256) {
        int r  = idx / (K / 4);
        int c4 = (idx % (K / 4)) * 4;
        *(float4*)&As[r * STR + c4] = *(const float4*)&emb[(size_t)(v0 + r) * K + c4];
        *(float4*)&Ws[r * STR + c4] = *(const float4*)&Wxh_w[(size_t)(h0 + r) * K + c4];
    }
    __syncthreads();

    const int lane = tid & 31, kg = tid >> 5;
    const int ln = lane & 7, lh = lane >> 3;
    const int kb = kg * (K / 8);

    u64 acc[4][8];
#pragma unroll
    for (int i = 0; i < 4; i++)
#pragma unroll
        for (int j = 0; j < 8; j++) acc[i][j] = 0ULL;

#pragma unroll 4
    for (int kk = 0; kk < K / 8; kk += 4) {
        float4 av[4], wv[8];
#pragma unroll
        for (int i = 0; i < 4; i++)
            av[i] = *(const float4*)&As[(ln + 8 * i) * STR + kb + kk];
#pragma unroll
        for (int j = 0; j < 8; j++)
            wv[j] = *(const float4*)&Ws[(lh + 4 * j) * STR + kb + kk];
#pragma unroll
        for (int i = 0; i < 4; i++) {
            u64 alo = ((const u64*)&av[i])[0], ahi = ((const u64*)&av[i])[1];
#pragma unroll
            for (int j = 0; j < 8; j++) {
                u64 wlo = ((const u64*)&wv[j])[0], whi = ((const u64*)&wv[j])[1];
                acc[i][j] = ffma2(alo, wlo, acc[i][j]);
                acc[i][j] = ffma2(ahi, whi, acc[i][j]);
            }
        }
    }

#pragma unroll
    for (int i = 0; i < 4; i++)
#pragma unroll
        for (int j = 0; j < 8; j++) {
            float2 f = *(float2*)&acc[i][j];
            red[kg * 1152 + (ln + 8 * i) * 36 + (lh + 4 * j)] = f.x + f.y;
        }
    __syncthreads();

    const int o_n = tid >> 3, o_h = (tid & 7) * 4;
    float4 s = make_float4(0.f, 0.f, 0.f, 0.f);
#pragma unroll
    for (int g = 0; g < 8; g++) {
        float4 p = *(const float4*)&red[g * 1152 + o_n * 36 + o_h];
        s.x += p.x; s.y += p.y; s.z += p.z; s.w += p.w;
    }
    float4 b4 = *(const float4*)&Wxh_b[h0 + o_h];
    s.x += b4.x; s.y += b4.y; s.z += b4.z; s.w += b4.w;
    *(float4*)&g_P[(size_t)(v0 + o_n) * HID + h0 + o_h] = s;
}

// ---------------------------------------------------------------------------
// rnn_kernel: ONE persistent launch, all 512 timesteps. NO clusters.
//   (R9 structure — the proven best — plus three handoff cuts:
//    st.release publish, 2-group cp.async overlap, packed f32x2 reduction.)
//   128 CTAs = 16 n-tiles x 8 h-tiles, 16n x 64h per CTA.
//   Sync = per-PRODUCER flags: CTA j publishes flag[j]=t+1 after its step-t
//   epilogue; consumer warp w polls only flag[w>>1] (its sole producer), then
//   cp.asyncs its 16n x 32k slice. Own-CTA warps (2j, 2j+1) get their slice
//   through SMEM written by the epilogue and skip polling entirely.
//   Flags are monotonic within a launch; the group's last-finishing CTA
//   resets them at kernel end (deterministic across graph replays).
// ---------------------------------------------------------------------------
__global__ void __launch_bounds__(NTHR, 1)
rnn_kernel(const int*   __restrict__ X,
           const float* __restrict__ Whh_w,
           const float* __restrict__ Whh_b,
           float*       __restrict__ out)
{
    extern __shared__ float sm[];
    float*  sm_h   = sm;                       // [16 w][16 n][32 k]   32 KB
    float2* sm_red = (float2*)(sm + 16 * 512); // [16 kg][16 n][32 l]  64 KB

    const int tid   = threadIdx.x;
    const int w     = tid >> 5;
    const int lane  = tid & 31;
    const int tile  = blockIdx.x >> 3;         // n-tile id (flag group)
    const int j_own = blockIdx.x & 7;          // own h-block id
    const int n0    = tile * NTILE;
    const int h0    = j_own * HTILE;
    const int hA    = h0 + 2 * lane;           // contiguous h pair
    const int hB    = hA + 1;

    const int  j_src   = w >> 1;               // producer this warp consumes
    const bool is_self = (j_src == j_own);

    // --- persistent weight registers: rows hA,hB, k in [32w, 32w+32) -------
    u64 wA[16], wB[16];
    {
        const u64* pa = (const u64*)&Whh_w[(size_t)hA * HID + w * 32];
        const u64* pb = (const u64*)&Whh_w[(size_t)hB * HID + w * 32];
#pragma unroll
        for (int i = 0; i < 16; i++) { wA[i] = pa[i]; wB[i] = pb[i]; }
    }

    unsigned int smem_w_base;
    {
        unsigned int a;
        asm("{ .reg .u64 t; cvta.to.shared.u64 t, %1; cvt.u32.u64 %0, t; }"
            : "=r"(a) : "l"(sm_h + w * 512));
        smem_w_base = a;
    }

    // epilogue ownership: thread (en, el) -> row n0+en, h-pair h0+2*el
    const int    en    = tid >> 5;
    const int    el    = tid & 31;
    const int    enab  = n0 + en;
    const float2 ebv   = *(const float2*)&Whh_b[h0 + 2 * el];
    // SMEM destination for own slice: warp 2*j_own + (el>=16), [n=en][kk=2el&31]
    float* sm_self = &sm_h[(2 * j_own + (el >> 4)) * 512 + en * 32 + ((2 * el) & 31)];

    unsigned* my_flag  = &g_flag[(tile * CL + j_own) * 64];
    unsigned* src_flag = &g_flag[(tile * CL + j_src) * 64];

    // preload step-0 gather
    float2 pv;
    {
        int xid = __ldg(&X[enab * LEN]);
        pv = __ldg((const float2*)&g_P[(size_t)xid * HID + h0 + 2 * el]);
    }

    for (int t = 0; t < LEN; t++) {
        float* dst = (t == LEN - 1) ? out : ((t & 1) ? g_h[1] : g_h[0]);
        const float* hin = (t & 1) ? g_h[0] : g_h[1];

        float sA = 0.f, sB = 0.f;

        if (t > 0) {
            if (!is_self) {
                // --- wait for our single producer -----------------------------
                if (lane == 0) {
                    unsigned g;
                    do {
                        asm volatile("ld.acquire.gpu.u32 %0, [%1];"
                                     : "=r"(g) : "l"(src_flag) : "memory");
                    } while (g < (unsigned)t);
                }
                __syncwarp();
                // --- pull its slice in TWO commit groups (rows 0-7, 8-15) ----
#pragma unroll
                for (int half = 0; half < 2; half++) {
#pragma unroll
                    for (int i = 0; i < 2; i++) {
                        int c  = half * 64 + i * 32 + lane;  // 16B chunk (0..127)
                        int n  = c >> 3;
                        int kq = c & 7;
                        const float* src =
                            &hin[(size_t)(n0 + n) * HID + w * 32 + kq * 4];
                        asm volatile("cp.async.cg.shared.global [%0], [%1], 16;"
                                     :: "r"(smem_w_base + c * 16), "l"(src)
                                     : "memory");
                    }
                    asm volatile("cp.async.commit_group;" ::: "memory");
                }
            }
            // (self warps: slice already in SMEM from last step's epilogue)

            // --- compute in two n-halves of 8; half 0 under half 1's arrival
#pragma unroll
            for (int half = 0; half < 2; half++) {
                if (!is_self) {
                    if (half == 0)
                        asm volatile("cp.async.wait_group 1;" ::: "memory");
                    else
                        asm volatile("cp.async.wait_group 0;" ::: "memory");
                }
                u64 aA[8], aB[8];
#pragma unroll
                for (int n = 0; n < 8; n++) { aA[n] = 0ULL; aB[n] = 0ULL; }
                const float* hp = sm_h + w * 512 + half * 8 * 32;
#pragma unroll
                for (int n = 0; n < 8; n++) {
                    const float4* row = (const float4*)(hp + n * 32);
                    u64 a0 = aA[n], a1 = aB[n];
#pragma unroll
                    for (int j = 0; j < 8; j++) {
                        float4 hv = row[j];
                        u64 lo = ((const u64*)&hv)[0];
                        u64 hi = ((const u64*)&hv)[1];
                        a0 = ffma2(lo, wA[2 * j],     a0);
                        a0 = ffma2(hi, wA[2 * j + 1], a0);
                        a1 = ffma2(lo, wB[2 * j],     a1);
                        a1 = ffma2(hi, wB[2 * j + 1], a1);
                    }
                    aA[n] = a0; aB[n] = a1;
                }
#pragma unroll
                for (int n = 0; n < 8; n++) {
                    float2 fa = *(float2*)&aA[n];
                    float2 fb = *(float2*)&aB[n];
                    sm_red[w * 512 + (half * 8 + n) * 32 + lane] =
                        make_float2(fa.x + fa.y, fb.x + fb.y);
                }
            }
            __syncthreads();

            // --- k-group reduction, packed f32x2 (order == R9 scalar) --------
            u64 r1 = 0ULL, r2 = 0ULL;
#pragma unroll
            for (int g = 0; g < 16; g += 2) {
                u64 v0 = *(const u64*)&sm_red[g * 512 + tid];
                u64 v1 = *(const u64*)&sm_red[(g + 1) * 512 + tid];
                r1 = fadd2(r1, v0);
                r2 = fadd2(r2, v1);
            }
            u64 rt = fadd2(r1, r2);
            float2 rr = *(float2*)&rt;
            sA = rr.x; sB = rr.y;
        }

        // --- fused epilogue: bias + P + tanh; publish to GMEM + own SMEM -----
        float2 o;
        o.x = tanhf(sA + ebv.x + pv.x);
        o.y = tanhf(sB + ebv.y + pv.y);
        *(float2*)&dst[(size_t)enab * HID + h0 + 2 * el] = o;
        *(float2*)sm_self = o;                 // self-warps read this next step

        if (t < LEN - 1) {
            // prefetch next step's gather (g_P immutable; hides under publish)
            int xid2 = __ldg(&X[enab * LEN + t + 1]);
            pv = __ldg((const float2*)&g_P[(size_t)xid2 * HID + h0 + 2 * el]);

            __syncthreads();                   // epilogue stores + STS done
            if (tid == 0) {
                // release store: orders this CTA's prior writes (made visible
                // to tid0's release by the syncthreads) before the flag
                asm volatile("st.release.gpu.u32 [%0], %1;"
                             :: "l"(my_flag), "r"((unsigned)(t + 1)) : "memory");
            }
        }
    }

    // --- end-of-kernel cleanup: last CTA of the group resets flags/counter --
    __syncthreads();
    if (tid == 0) {
        unsigned old;
        asm volatile("atom.acq_rel.gpu.global.add.u32 %0, [%1], %2;"
                     : "=r"(old) : "l"(&g_cnt[tile * 64]), "r"(1u) : "memory");
        if (old == CL - 1) {
#pragma unroll
            for (int j = 0; j < CL; j++)
                asm volatile("st.relaxed.gpu.u32 [%0], %1;"
                             :: "l"(&g_flag[(tile * CL + j) * 64]), "r"(0u)
                             : "memory");
            asm volatile("st.relaxed.gpu.u32 [%0], %1;"
                         :: "l"(&g_cnt[tile * 64]), "r"(0u) : "memory");
        }
    }
}

// ---------------------------------------------------------------------------
extern "C" void kernel_launch(void* const* d_in, const int* in_sizes, int n_in,
                              void* d_out, int out_size) {
    const int*   X     = (const int*)d_in[0];
    const float* emb   = (const float*)d_in[1];
    const float* Whh_w = (const float*)d_in[2];
    const float* Whh_b = (const float*)d_in[3];
    const float* Wxh_w = (const float*)d_in[4];
    const float* Wxh_b = (const float*)d_in[5];
    float* out = (float*)d_out;

    const size_t sm_proj = (size_t)(64 * (EMB + 4) + 8 * 32 * 36) * sizeof(float); // ~101 KB
    const size_t sm_rnn  = (size_t)(16 * 512) * sizeof(float)                      // 32 KB h
                         + (size_t)(16 * 512) * sizeof(float2);                    // 64 KB red
    cudaFuncSetAttribute(proj_kernel, cudaFuncAttributeMaxDynamicSharedMemorySize, (int)sm_proj);
    cudaFuncSetAttribute(rnn_kernel,  cudaFuncAttributeMaxDynamicSharedMemorySize, (int)sm_rnn);

    // 1) P = emb @ Wxh^T + Wxh_b
    proj_kernel<<<dim3(VOCAB / 32, HID / 32), 256, sm_proj>>>(emb, Wxh_w, Wxh_b);

    // 2) all 512 timesteps in one persistent launch
    rnn_kernel<<<GRID, NTHR, sm_rnn>>>(X, Whh_w, Whh_b, out);
}